// round 2
// baseline (speedup 1.0000x reference)
#include <cuda_runtime.h>

#define TDIM 200
#define PDIM 784
#define BDIM 256
#define PI_F 3.14159265358979323846f

// Scratch (no allocation allowed): c[f], D[f][t], u partials (4 p-splits)
__device__ float2 g_c[TDIM];
__device__ float2 g_D[TDIM * TDIM];
__device__ float2 g_u[4][BDIM * TDIM];

// ---------------------------------------------------------------------------
// K1: c[f] = DFT(waveform)[f] * envelope[f]      (1 block, 200 threads)
// ---------------------------------------------------------------------------
__global__ void k_c(const float* __restrict__ wre, const float* __restrict__ wim,
                    const float* __restrict__ ere, const float* __restrict__ eim) {
    __shared__ float2 tw[TDIM];
    __shared__ float wr_s[TDIM], wi_s[TDIM];
    int f = threadIdx.x;  // 0..199
    {
        float ang = (2.0f * PI_F / TDIM) * (float)f;
        float s, c;
        sincosf(ang, &s, &c);
        tw[f] = make_float2(c, s);
        wr_s[f] = wre[f];
        wi_s[f] = wim[f];
    }
    __syncthreads();
    float ar = 0.f, ai = 0.f;
    int m = 0;  // (f*t) mod 200, exact twiddle index
    for (int t = 0; t < TDIM; t++) {
        float2 w = tw[m];
        m += f; if (m >= TDIM) m -= TDIM;
        float xr = wr_s[t], xi = wi_s[t];
        // (xr + i xi) * e^{-i ang} = (xr*cos + xi*sin) + i(xi*cos - xr*sin)
        ar += xr * w.x + xi * w.y;
        ai += xi * w.x - xr * w.y;
    }
    float er = ere[f], ei = eim[f];
    g_c[f] = make_float2(ar * er - ai * ei, ar * ei + ai * er);
}

// ---------------------------------------------------------------------------
// K2: D[f][t] = c[f] * e^{+2pi i f t / T} / T     (200 blocks x 200 threads)
// ---------------------------------------------------------------------------
__global__ void k_D() {
    int f = blockIdx.x, t = threadIdx.x;
    int m = (f * t) % TDIM;
    float ang = (2.0f * PI_F / TDIM) * (float)m;
    float s, co;
    sincosf(ang, &s, &co);
    float2 c = g_c[f];
    const float inv = 1.0f / TDIM;
    g_D[f * TDIM + t] = make_float2((c.x * co - c.y * s) * inv,
                                    (c.x * s + c.y * co) * inv);
}

// ---------------------------------------------------------------------------
// K3: u[b][f] = sum_p x[b][p]*v[p] * (Sre[p][f] + i Sim[p][f])
//     grid (4 p-splits, 32 b-tiles), block 200 threads (f), 8 batches/thread
// ---------------------------------------------------------------------------
__global__ void __launch_bounds__(200) k_u(const float* __restrict__ x,
                                           const float* __restrict__ v,
                                           const float* __restrict__ sre,
                                           const float* __restrict__ sim) {
    __shared__ float xv_s[8][196];
    const int s  = blockIdx.x;        // p-split
    const int b0 = blockIdx.y * 8;    // batch tile base
    const int p0 = s * 196;
    const int tid = threadIdx.x;

    for (int idx = tid; idx < 8 * 196; idx += 200) {
        int j = idx / 196, pp = idx % 196;
        xv_s[j][pp] = x[(b0 + j) * PDIM + p0 + pp] * v[p0 + pp];
    }
    __syncthreads();

    const int f = tid;
    float ur[8], ui[8];
#pragma unroll
    for (int j = 0; j < 8; j++) { ur[j] = 0.f; ui[j] = 0.f; }

    const float* srp = sre + (size_t)p0 * TDIM + f;
    const float* sip = sim + (size_t)p0 * TDIM + f;
#pragma unroll 4
    for (int pp = 0; pp < 196; pp++) {
        float a_re = srp[(size_t)pp * TDIM];
        float a_im = sip[(size_t)pp * TDIM];
#pragma unroll
        for (int j = 0; j < 8; j++) {
            float a = xv_s[j][pp];
            ur[j] = fmaf(a, a_re, ur[j]);
            ui[j] = fmaf(a, a_im, ui[j]);
        }
    }
#pragma unroll
    for (int j = 0; j < 8; j++)
        g_u[s][(b0 + j) * TDIM + f] = make_float2(ur[j], ui[j]);
}

// ---------------------------------------------------------------------------
// K4: r[b][t] = sum_f (u_re*D_re - u_im*D_im); chunk-max over 20; 10x10 linear
//     grid 128 blocks, block (200 t, 2 b)
// ---------------------------------------------------------------------------
__global__ void __launch_bounds__(400) k_out(const float* __restrict__ lin_w,
                                             const float* __restrict__ lin_b,
                                             float* __restrict__ out) {
    __shared__ float2 u_s[2][TDIM];
    __shared__ float vals[2][TDIM];
    __shared__ float cm_s[2][10];
    const int t  = threadIdx.x;
    const int ty = threadIdx.y;
    const int b0 = blockIdx.x * 2;

    // gather + reduce the 4 p-split partials of u for this block's 2 batches
    for (int idx = ty * TDIM + t; idx < 2 * TDIM; idx += 400) {
        int bb = idx / TDIM, f = idx % TDIM;
        float2 acc = make_float2(0.f, 0.f);
#pragma unroll
        for (int s = 0; s < 4; s++) {
            float2 p = g_u[s][(b0 + bb) * TDIM + f];
            acc.x += p.x;
            acc.y += p.y;
        }
        u_s[bb][f] = acc;
    }
    __syncthreads();

    float r = 0.f;
#pragma unroll 4
    for (int f = 0; f < TDIM; f++) {
        float2 d  = g_D[f * TDIM + t];
        float2 uu = u_s[ty][f];
        r = fmaf(uu.x, d.x, r);
        r = fmaf(-uu.y, d.y, r);
    }
    vals[ty][t] = sqrtf(fmaf(r, r, 1e-20f));
    __syncthreads();

    if (t < 10) {
        float m = 0.f;
#pragma unroll
        for (int k = 0; k < 20; k++) m = fmaxf(m, vals[ty][t * 20 + k]);
        cm_s[ty][t] = m;
    }
    __syncthreads();

    if (t < 10) {
        int b = b0 + ty;
        float o = lin_b[t];
#pragma unroll
        for (int c = 0; c < 10; c++) o = fmaf(cm_s[ty][c], lin_w[t * 10 + c], o);
        out[b * 10 + t] = o;
    }
}

// ---------------------------------------------------------------------------
extern "C" void kernel_launch(void* const* d_in, const int* in_sizes, int n_in,
                              void* d_out, int out_size) {
    const float* x   = (const float*)d_in[0];  // [256, 784]
    const float* v   = (const float*)d_in[1];  // [784]
    const float* sre = (const float*)d_in[2];  // [784, 200]
    const float* sim = (const float*)d_in[3];  // [784, 200]
    const float* ere = (const float*)d_in[4];  // [200]
    const float* eim = (const float*)d_in[5];  // [200]
    const float* wre = (const float*)d_in[6];  // [200]
    const float* wim = (const float*)d_in[7];  // [200]
    const float* lw  = (const float*)d_in[8];  // [10, 10]
    const float* lb  = (const float*)d_in[9];  // [10]
    float* out = (float*)d_out;                // [256, 10] float32

    k_c<<<1, TDIM>>>(wre, wim, ere, eim);
    k_D<<<TDIM, TDIM>>>();
    k_u<<<dim3(4, 32), 200>>>(x, v, sre, sim);
    k_out<<<128, dim3(TDIM, 2)>>>(lw, lb, out);
}

// round 3
// speedup vs baseline: 1.0054x; 1.0054x over previous
#include <cuda_runtime.h>

#define TDIM 200
#define PDIM 784
#define BDIM 256
#define PI_F 3.14159265358979323846f

// Scratch (no allocation allowed): c[f], D[f][t], u partials (4 p-splits)
__device__ float2 g_c[TDIM];
__device__ float2 g_D[TDIM * TDIM];
__device__ float2 g_u[4][BDIM * TDIM];

// ---------------------------------------------------------------------------
// K1: c[f] = DFT(waveform)[f] * envelope[f]      (1 block, 200 threads)
// ---------------------------------------------------------------------------
__global__ void k_c(const float* __restrict__ wre, const float* __restrict__ wim,
                    const float* __restrict__ ere, const float* __restrict__ eim) {
    __shared__ float2 tw[TDIM];
    __shared__ float wr_s[TDIM], wi_s[TDIM];
    int f = threadIdx.x;  // 0..199
    {
        float ang = (2.0f * PI_F / TDIM) * (float)f;
        float s, c;
        sincosf(ang, &s, &c);
        tw[f] = make_float2(c, s);
        wr_s[f] = wre[f];
        wi_s[f] = wim[f];
    }
    __syncthreads();
    float ar = 0.f, ai = 0.f;
    int m = 0;  // (f*t) mod 200, exact twiddle index
    for (int t = 0; t < TDIM; t++) {
        float2 w = tw[m];
        m += f; if (m >= TDIM) m -= TDIM;
        float xr = wr_s[t], xi = wi_s[t];
        // (xr + i xi) * e^{-i ang} = (xr*cos + xi*sin) + i(xi*cos - xr*sin)
        ar += xr * w.x + xi * w.y;
        ai += xi * w.x - xr * w.y;
    }
    float er = ere[f], ei = eim[f];
    g_c[f] = make_float2(ar * er - ai * ei, ar * ei + ai * er);
}

// ---------------------------------------------------------------------------
// K2: D[f][t] = c[f] * e^{+2pi i f t / T} / T     (200 blocks x 200 threads)
// ---------------------------------------------------------------------------
__global__ void k_D() {
    int f = blockIdx.x, t = threadIdx.x;
    int m = (f * t) % TDIM;
    float ang = (2.0f * PI_F / TDIM) * (float)m;
    float s, co;
    sincosf(ang, &s, &co);
    float2 c = g_c[f];
    const float inv = 1.0f / TDIM;
    g_D[f * TDIM + t] = make_float2((c.x * co - c.y * s) * inv,
                                    (c.x * s + c.y * co) * inv);
}

// ---------------------------------------------------------------------------
// K3: u[b][f] = sum_p x[b][p]*v[p] * (Sre[p][f] + i Sim[p][f])
//     grid (4 p-splits, 32 b-tiles), block 200 threads (f), 8 batches/thread
// ---------------------------------------------------------------------------
__global__ void __launch_bounds__(200) k_u(const float* __restrict__ x,
                                           const float* __restrict__ v,
                                           const float* __restrict__ sre,
                                           const float* __restrict__ sim) {
    __shared__ float xv_s[8][196];
    const int s  = blockIdx.x;        // p-split
    const int b0 = blockIdx.y * 8;    // batch tile base
    const int p0 = s * 196;
    const int tid = threadIdx.x;

    for (int idx = tid; idx < 8 * 196; idx += 200) {
        int j = idx / 196, pp = idx % 196;
        xv_s[j][pp] = x[(b0 + j) * PDIM + p0 + pp] * v[p0 + pp];
    }
    __syncthreads();

    const int f = tid;
    float ur[8], ui[8];
#pragma unroll
    for (int j = 0; j < 8; j++) { ur[j] = 0.f; ui[j] = 0.f; }

    const float* srp = sre + (size_t)p0 * TDIM + f;
    const float* sip = sim + (size_t)p0 * TDIM + f;
#pragma unroll 4
    for (int pp = 0; pp < 196; pp++) {
        float a_re = srp[(size_t)pp * TDIM];
        float a_im = sip[(size_t)pp * TDIM];
#pragma unroll
        for (int j = 0; j < 8; j++) {
            float a = xv_s[j][pp];
            ur[j] = fmaf(a, a_re, ur[j]);
            ui[j] = fmaf(a, a_im, ui[j]);
        }
    }
#pragma unroll
    for (int j = 0; j < 8; j++)
        g_u[s][(b0 + j) * TDIM + f] = make_float2(ur[j], ui[j]);
}

// ---------------------------------------------------------------------------
// K4: r[b][t] = sum_f (u_re*D_re - u_im*D_im); chunk-max over 20; 10x10 linear
//     grid 128 blocks, block (200 t, 2 b)
// ---------------------------------------------------------------------------
__global__ void __launch_bounds__(400) k_out(const float* __restrict__ lin_w,
                                             const float* __restrict__ lin_b,
                                             float* __restrict__ out) {
    __shared__ float2 u_s[2][TDIM];
    __shared__ float vals[2][TDIM];
    __shared__ float cm_s[2][10];
    const int t  = threadIdx.x;
    const int ty = threadIdx.y;
    const int b0 = blockIdx.x * 2;

    // gather + reduce the 4 p-split partials of u for this block's 2 batches
    for (int idx = ty * TDIM + t; idx < 2 * TDIM; idx += 400) {
        int bb = idx / TDIM, f = idx % TDIM;
        float2 acc = make_float2(0.f, 0.f);
#pragma unroll
        for (int s = 0; s < 4; s++) {
            float2 p = g_u[s][(b0 + bb) * TDIM + f];
            acc.x += p.x;
            acc.y += p.y;
        }
        u_s[bb][f] = acc;
    }
    __syncthreads();

    float r = 0.f;
#pragma unroll 4
    for (int f = 0; f < TDIM; f++) {
        float2 d  = g_D[f * TDIM + t];
        float2 uu = u_s[ty][f];
        r = fmaf(uu.x, d.x, r);
        r = fmaf(-uu.y, d.y, r);
    }
    vals[ty][t] = sqrtf(fmaf(r, r, 1e-20f));
    __syncthreads();

    if (t < 10) {
        float m = 0.f;
#pragma unroll
        for (int k = 0; k < 20; k++) m = fmaxf(m, vals[ty][t * 20 + k]);
        cm_s[ty][t] = m;
    }
    __syncthreads();

    if (t < 10) {
        int b = b0 + ty;
        float o = lin_b[t];
#pragma unroll
        for (int c = 0; c < 10; c++) o = fmaf(cm_s[ty][c], lin_w[t * 10 + c], o);
        out[b * 10 + t] = o;
    }
}

// ---------------------------------------------------------------------------
extern "C" void kernel_launch(void* const* d_in, const int* in_sizes, int n_in,
                              void* d_out, int out_size) {
    const float* x   = (const float*)d_in[0];  // [256, 784]
    const float* v   = (const float*)d_in[1];  // [784]
    const float* sre = (const float*)d_in[2];  // [784, 200]
    const float* sim = (const float*)d_in[3];  // [784, 200]
    const float* ere = (const float*)d_in[4];  // [200]
    const float* eim = (const float*)d_in[5];  // [200]
    const float* wre = (const float*)d_in[6];  // [200]
    const float* wim = (const float*)d_in[7];  // [200]
    const float* lw  = (const float*)d_in[8];  // [10, 10]
    const float* lb  = (const float*)d_in[9];  // [10]
    float* out = (float*)d_out;                // [256, 10] float32

    k_c<<<1, TDIM>>>(wre, wim, ere, eim);
    k_D<<<TDIM, TDIM>>>();
    k_u<<<dim3(4, 32), 200>>>(x, v, sre, sim);
    k_out<<<128, dim3(TDIM, 2)>>>(lw, lb, out);
}

// round 4
// speedup vs baseline: 1.3930x; 1.3855x over previous
#include <cuda_runtime.h>

#define TDIM 200
#define PDIM 784
#define BDIM 256
#define PSPLIT 8
#define PCHUNK 98     // 784 / 8
#define BTILE 16
#define PI_F 3.14159265358979323846f

// Scratch (no allocation allowed)
__device__ __align__(16) float2 g_Dt[TDIM * TDIM];       // transposed: [t][f]
__device__ float2 g_u[PSPLIT][BDIM * TDIM];              // p-split partials of u

// ---------------------------------------------------------------------------
// K1 (fused): block f computes c[f] = DFT(waveform)[f]*env[f] via reduction,
// then writes D^T[t][f] = c[f] * e^{+2pi i f t / T} / T.
// grid 200 (f), block 200 (t)
// ---------------------------------------------------------------------------
__global__ void __launch_bounds__(TDIM) k_Dc(const float* __restrict__ wre,
                                             const float* __restrict__ wim,
                                             const float* __restrict__ ere,
                                             const float* __restrict__ eim) {
    __shared__ float rr[TDIM], ri[TDIM];
    __shared__ float2 c_sh;
    const int f = blockIdx.x, t = threadIdx.x;
    const int m = (f * t) % TDIM;                 // exact twiddle index
    float ang = (2.0f * PI_F / TDIM) * (float)m;
    float si, co;
    sincosf(ang, &si, &co);
    float xr = wre[t], xi = wim[t];
    // x * e^{-i ang}
    rr[t] = xr * co + xi * si;
    ri[t] = xi * co - xr * si;
    __syncthreads();
    if (t < 100) { rr[t] += rr[t + 100]; ri[t] += ri[t + 100]; }
    __syncthreads();
    if (t < 50)  { rr[t] += rr[t + 50];  ri[t] += ri[t + 50]; }
    __syncthreads();
    if (t < 25)  { rr[t] += rr[t + 25];  ri[t] += ri[t + 25]; }
    __syncthreads();
    if (t < 32) {
        float vr = (t < 25) ? rr[t] : 0.f;
        float vi = (t < 25) ? ri[t] : 0.f;
#pragma unroll
        for (int off = 16; off; off >>= 1) {
            vr += __shfl_down_sync(0xffffffffu, vr, off);
            vi += __shfl_down_sync(0xffffffffu, vi, off);
        }
        if (t == 0) {
            float er = ere[f], ei = eim[f];
            c_sh = make_float2(vr * er - vi * ei, vr * ei + vi * er);
        }
    }
    __syncthreads();
    float2 c = c_sh;
    const float inv = 1.0f / TDIM;
    // c * e^{+i ang} / T, stored transposed
    g_Dt[t * TDIM + f] = make_float2((c.x * co - c.y * si) * inv,
                                     (c.x * si + c.y * co) * inv);
}

// ---------------------------------------------------------------------------
// K2: u[b][f] = sum_p x[b][p]*v[p] * S[p][f]   (complex)
// grid (8 p-splits, 16 b-tiles) = 128 blocks, block 200 threads (f)
// 16 batches per block; S loads software-pipelined in groups of 7 (98 = 7*14)
// ---------------------------------------------------------------------------
__global__ void __launch_bounds__(TDIM) k_u(const float* __restrict__ x,
                                            const float* __restrict__ v,
                                            const float* __restrict__ sre,
                                            const float* __restrict__ sim) {
    __shared__ __align__(16) float xv_s[PCHUNK][BTILE];
    const int s  = blockIdx.x;
    const int b0 = blockIdx.y * BTILE;
    const int p0 = s * PCHUNK;
    const int tid = threadIdx.x;

    for (int idx = tid; idx < PCHUNK * BTILE; idx += TDIM) {
        int pp = idx >> 4, j = idx & 15;
        xv_s[pp][j] = x[(b0 + j) * PDIM + p0 + pp] * v[p0 + pp];
    }
    __syncthreads();

    const int f = tid;
    float ur[BTILE], ui[BTILE];
#pragma unroll
    for (int j = 0; j < BTILE; j++) { ur[j] = 0.f; ui[j] = 0.f; }

    const float* srp = sre + (size_t)p0 * TDIM + f;
    const float* sip = sim + (size_t)p0 * TDIM + f;

    const int G = 7;                 // 14 groups of 7
    float cre[G], cim[G], nre[G], nim[G];
#pragma unroll
    for (int k = 0; k < G; k++) {
        cre[k] = srp[(size_t)k * TDIM];
        cim[k] = sip[(size_t)k * TDIM];
    }
    for (int g = 0; g < 14; g++) {
        if (g < 13) {
            int base = (g + 1) * G;
#pragma unroll
            for (int k = 0; k < G; k++) {
                nre[k] = srp[(size_t)(base + k) * TDIM];
                nim[k] = sip[(size_t)(base + k) * TDIM];
            }
        }
        const int pb = g * G;
#pragma unroll
        for (int k = 0; k < G; k++) {
            const float4* xv4 = (const float4*)xv_s[pb + k];
#pragma unroll
            for (int q = 0; q < 4; q++) {
                float4 a = xv4[q];
                ur[q*4+0] = fmaf(a.x, cre[k], ur[q*4+0]);
                ui[q*4+0] = fmaf(a.x, cim[k], ui[q*4+0]);
                ur[q*4+1] = fmaf(a.y, cre[k], ur[q*4+1]);
                ui[q*4+1] = fmaf(a.y, cim[k], ui[q*4+1]);
                ur[q*4+2] = fmaf(a.z, cre[k], ur[q*4+2]);
                ui[q*4+2] = fmaf(a.z, cim[k], ui[q*4+2]);
                ur[q*4+3] = fmaf(a.w, cre[k], ur[q*4+3]);
                ui[q*4+3] = fmaf(a.w, cim[k], ui[q*4+3]);
            }
        }
#pragma unroll
        for (int k = 0; k < G; k++) { cre[k] = nre[k]; cim[k] = nim[k]; }
    }
#pragma unroll
    for (int j = 0; j < BTILE; j++)
        g_u[s][(b0 + j) * TDIM + f] = make_float2(ur[j], ui[j]);
}

// ---------------------------------------------------------------------------
// K3: r[b][t] = sum_f Re(u[b][f] * D[f][t]); chunk-max; 10x10 linear
// grid 128 (2 batches), block (200 t, 2 b). D^T streamed via LDG.128.
// ---------------------------------------------------------------------------
__global__ void __launch_bounds__(2 * TDIM) k_out(const float* __restrict__ lw,
                                                  const float* __restrict__ lb,
                                                  float* __restrict__ out) {
    __shared__ __align__(16) float2 u_s[2][TDIM];
    __shared__ float vals[2][TDIM];
    __shared__ float cm[2][10];
    const int t  = threadIdx.x;
    const int ty = threadIdx.y;
    const int b0 = blockIdx.x * 2;

    // gather + reduce the 8 p-split partials of u (one (b,f) per thread)
    {
        float2 acc = make_float2(0.f, 0.f);
#pragma unroll
        for (int s = 0; s < PSPLIT; s++) {
            float2 p = g_u[s][(b0 + ty) * TDIM + t];
            acc.x += p.x;
            acc.y += p.y;
        }
        u_s[ty][t] = acc;
    }
    __syncthreads();

    const float4* dp = (const float4*)(g_Dt + (size_t)t * TDIM);  // row t, 100 float4
    const float4* up = (const float4*)u_s[ty];                    // broadcast
    float r0 = 0.f, r1 = 0.f;
#pragma unroll 10
    for (int j = 0; j < TDIM / 2; j++) {
        float4 d = dp[j];   // (Dre[2j], Dim[2j], Dre[2j+1], Dim[2j+1])
        float4 u = up[j];   // (ure[2j], uim[2j], ure[2j+1], uim[2j+1])
        r0 = fmaf(u.x, d.x, r0);
        r0 = fmaf(-u.y, d.y, r0);
        r1 = fmaf(u.z, d.z, r1);
        r1 = fmaf(-u.w, d.w, r1);
    }
    float r = r0 + r1;
    vals[ty][t] = sqrtf(fmaf(r, r, 1e-20f));
    __syncthreads();

    if (t < 10) {
        float mx = 0.f;
#pragma unroll
        for (int k = 0; k < 20; k++) mx = fmaxf(mx, vals[ty][t * 20 + k]);
        cm[ty][t] = mx;
    }
    __syncthreads();

    if (t < 10) {
        float o = lb[t];
#pragma unroll
        for (int c2 = 0; c2 < 10; c2++) o = fmaf(cm[ty][c2], lw[t * 10 + c2], o);
        out[(b0 + ty) * 10 + t] = o;
    }
}

// ---------------------------------------------------------------------------
extern "C" void kernel_launch(void* const* d_in, const int* in_sizes, int n_in,
                              void* d_out, int out_size) {
    const float* x   = (const float*)d_in[0];  // [256, 784]
    const float* v   = (const float*)d_in[1];  // [784]
    const float* sre = (const float*)d_in[2];  // [784, 200]
    const float* sim = (const float*)d_in[3];  // [784, 200]
    const float* ere = (const float*)d_in[4];  // [200]
    const float* eim = (const float*)d_in[5];  // [200]
    const float* wre = (const float*)d_in[6];  // [200]
    const float* wim = (const float*)d_in[7];  // [200]
    const float* lw  = (const float*)d_in[8];  // [10, 10]
    const float* lb  = (const float*)d_in[9];  // [10]
    float* out = (float*)d_out;                // [256, 10] float32

    k_Dc<<<TDIM, TDIM>>>(wre, wim, ere, eim);
    k_u<<<dim3(PSPLIT, BDIM / BTILE), TDIM>>>(x, v, sre, sim);
    k_out<<<BDIM / 2, dim3(TDIM, 2)>>>(lw, lb, out);
}

// round 6
// speedup vs baseline: 1.6498x; 1.1844x over previous
#include <cuda_runtime.h>

#define TDIM 200
#define PDIM 784
#define BDIM 256
#define PSPLIT 8
#define PCHUNK 98     // 784 / 8
#define BTILE 16
#define PI_F 3.14159265358979323846f

typedef unsigned long long ull;

// Scratch (no allocation allowed)
__device__ float2 g_c[TDIM];
__device__ __align__(16) float2 g_Dt[TDIM * TDIM];   // [t][f], imag NEGATED, /T
__device__ float2 g_u[PSPLIT][BDIM * TDIM];          // p-split partials of u

// ---- packed f32x2 helpers (FFMA2: ptxas never auto-fuses this) -----------
__device__ __forceinline__ ull pk2(float x, float y) {
    ull r; asm("mov.b64 %0, {%1, %2};" : "=l"(r) : "f"(x), "f"(y)); return r;
}
__device__ __forceinline__ void upk2(ull v, float& x, float& y) {
    asm("mov.b64 {%0, %1}, %2;" : "=f"(x), "=f"(y) : "l"(v));
}
__device__ __forceinline__ void fma2(ull& acc, ull a, ull b) {
    asm("fma.rn.f32x2 %0, %1, %2, %0;" : "+l"(acc) : "l"(a), "l"(b));
}

// ---------------------------------------------------------------------------
// K1 (fused): blocks (s<8, by): u[b][f] = sum_p xv[b][p] * S[p][f]  (complex)
//             block  (s==8, by==0): c[f] = DFT(waveform)[f] * env[f]
// grid (9, 16) = 144 blocks (1 wave on 148 SMs; c-block rides free)
// ---------------------------------------------------------------------------
__global__ void __launch_bounds__(TDIM) k_uc(const float* __restrict__ x,
                                             const float* __restrict__ v,
                                             const float* __restrict__ sre,
                                             const float* __restrict__ sim,
                                             const float* __restrict__ wre,
                                             const float* __restrict__ wim,
                                             const float* __restrict__ ere,
                                             const float* __restrict__ eim) {
    __shared__ __align__(16) float2 xv_s[PCHUNK][BTILE];  // (a, a) duplicated
    __shared__ float2 tw[TDIM];
    __shared__ float wr_s[TDIM], wi_s[TDIM];

    const int s   = blockIdx.x;
    const int tid = threadIdx.x;

    if (s == PSPLIT) {
        // ---- c[f] branch: one block, 200-point DFT via shared twiddles ----
        if (blockIdx.y != 0) return;
        const int f = tid;
        {
            float ang = (2.0f * PI_F / TDIM) * (float)f;
            float si, co;
            sincosf(ang, &si, &co);
            tw[f] = make_float2(co, si);
            wr_s[f] = wre[f];
            wi_s[f] = wim[f];
        }
        __syncthreads();
        float ar = 0.f, ai = 0.f;
        int m = 0;  // (f*t) mod 200 exact
        for (int t = 0; t < TDIM; t++) {
            float2 w = tw[m];
            m += f; if (m >= TDIM) m -= TDIM;
            float xr = wr_s[t], xi = wi_s[t];
            ar += xr * w.x + xi * w.y;   // x * e^{-i ang}
            ai += xi * w.x - xr * w.y;
        }
        float er = ere[f], ei = eim[f];
        g_c[f] = make_float2(ar * er - ai * ei, ar * ei + ai * er);
        return;
    }

    // ---- u branch ----
    const int b0 = blockIdx.y * BTILE;
    const int p0 = s * PCHUNK;

    for (int idx = tid; idx < PCHUNK * BTILE; idx += TDIM) {
        int pp = idx >> 4, j = idx & 15;
        float a = x[(b0 + j) * PDIM + p0 + pp] * v[p0 + pp];
        xv_s[pp][j] = make_float2(a, a);
    }
    __syncthreads();

    const int f = tid;
    ull acc[BTILE];   // acc[j] accumulates (u_re, u_im) for batch b0+j
#pragma unroll
    for (int j = 0; j < BTILE; j++) acc[j] = 0ull;

    const float* srp = sre + (size_t)p0 * TDIM + f;
    const float* sip = sim + (size_t)p0 * TDIM + f;

    const int G = 7;  // 14 groups of 7 (98 = 7*14), software pipelined
    float cre[G], cim[G], nre[G], nim[G];
#pragma unroll
    for (int k = 0; k < G; k++) {
        cre[k] = srp[(size_t)k * TDIM];
        cim[k] = sip[(size_t)k * TDIM];
    }
    for (int g = 0; g < 14; g++) {
        if (g < 13) {
            int base = (g + 1) * G;
#pragma unroll
            for (int k = 0; k < G; k++) {
                nre[k] = srp[(size_t)(base + k) * TDIM];
                nim[k] = sip[(size_t)(base + k) * TDIM];
            }
        }
        const int pb = g * G;
#pragma unroll
        for (int k = 0; k < G; k++) {
            ull bpk = pk2(cre[k], cim[k]);               // (sre, sim)
            const float4* xv4 = (const float4*)xv_s[pb + k];
            // row = 16 float2 = 8 float4; xv4[q] = (a_{2q},a_{2q},a_{2q+1},a_{2q+1})
#pragma unroll
            for (int q = 0; q < 8; q++) {
                float4 a = xv4[q];
                fma2(acc[2 * q + 0], pk2(a.x, a.y), bpk);  // batch 2q
                fma2(acc[2 * q + 1], pk2(a.z, a.w), bpk);  // batch 2q+1
            }
        }
#pragma unroll
        for (int k = 0; k < G; k++) { cre[k] = nre[k]; cim[k] = nim[k]; }
    }
#pragma unroll
    for (int j = 0; j < BTILE; j++) {
        float ur, ui_;
        upk2(acc[j], ur, ui_);
        g_u[s][(b0 + j) * TDIM + f] = make_float2(ur, ui_);
    }
}

// ---------------------------------------------------------------------------
// K2: D^T[t][f] = (Re, -Im) of c[f] * e^{+2pi i f t/T} / T
// grid 200 (t), block 200 (f): fully coalesced float2 stores
// ---------------------------------------------------------------------------
__global__ void __launch_bounds__(TDIM) k_D() {
    const int t = blockIdx.x, f = threadIdx.x;
    int m = (f * t) % TDIM;
    float ang = (2.0f * PI_F / TDIM) * (float)m;
    float si, co;
    sincosf(ang, &si, &co);
    float2 c = g_c[f];
    const float inv = 1.0f / TDIM;
    g_Dt[t * TDIM + f] = make_float2((c.x * co - c.y * si) * inv,
                                     -(c.x * si + c.y * co) * inv);
}

// ---------------------------------------------------------------------------
// K3: r[b][t] = Re(sum_f u[b][f]*D[f][t]); chunk-max; 10x10 linear
// grid 128 blocks, block 200 (t); each thread does BOTH batches off one
// D-row stream (halves D traffic). Packed FFMA2 inner loop.
// ---------------------------------------------------------------------------
__global__ void __launch_bounds__(TDIM) k_out(const float* __restrict__ lw,
                                              const float* __restrict__ lb,
                                              float* __restrict__ out) {
    __shared__ __align__(16) float2 u_s[2][TDIM];
    __shared__ float vals[2][TDIM];
    __shared__ float cm[2][10];
    const int t  = threadIdx.x;
    const int b0 = blockIdx.x * 2;

    // gather + reduce the 8 p-split partials of u for both batches
#pragma unroll
    for (int bb = 0; bb < 2; bb++) {
        float2 a = make_float2(0.f, 0.f);
#pragma unroll
        for (int s = 0; s < PSPLIT; s++) {
            float2 p = g_u[s][(b0 + bb) * TDIM + t];
            a.x += p.x; a.y += p.y;
        }
        u_s[bb][t] = a;
    }
    __syncthreads();

    const float4* dp  = (const float4*)(g_Dt + (size_t)t * TDIM);  // 100 float4
    const float4* up0 = (const float4*)u_s[0];
    const float4* up1 = (const float4*)u_s[1];
    ull a0a = 0, a0b = 0, a1a = 0, a1b = 0;
#pragma unroll 10
    for (int j = 0; j < TDIM / 2; j++) {
        float4 d  = dp[j];    // (dre, -dim) x2
        float4 u0 = up0[j];   // (ure, uim) x2
        float4 u1 = up1[j];
        fma2(a0a, pk2(u0.x, u0.y), pk2(d.x, d.y));
        fma2(a0b, pk2(u0.z, u0.w), pk2(d.z, d.w));
        fma2(a1a, pk2(u1.x, u1.y), pk2(d.x, d.y));
        fma2(a1b, pk2(u1.z, u1.w), pk2(d.z, d.w));
    }
    {
        float x0, y0, x1, y1;
        upk2(a0a, x0, y0); upk2(a0b, x1, y1);
        float r = (x0 + y0) + (x1 + y1);   // sum(ure*dre - uim*dim)
        vals[0][t] = sqrtf(fmaf(r, r, 1e-20f));
        upk2(a1a, x0, y0); upk2(a1b, x1, y1);
        r = (x0 + y0) + (x1 + y1);
        vals[1][t] = sqrtf(fmaf(r, r, 1e-20f));
    }
    __syncthreads();

    if (t < 20) {
        int bb = t / 10, c = t % 10;
        float mx = 0.f;
#pragma unroll
        for (int k = 0; k < 20; k++) mx = fmaxf(mx, vals[bb][c * 20 + k]);
        cm[bb][c] = mx;
    }
    __syncthreads();

    if (t < 20) {
        int bb = t / 10, c = t % 10;
        float o = lb[c];
#pragma unroll
        for (int cc = 0; cc < 10; cc++) o = fmaf(cm[bb][cc], lw[c * 10 + cc], o);
        out[(b0 + bb) * 10 + c] = o;
    }
}

// ---------------------------------------------------------------------------
extern "C" void kernel_launch(void* const* d_in, const int* in_sizes, int n_in,
                              void* d_out, int out_size) {
    const float* x   = (const float*)d_in[0];  // [256, 784]
    const float* v   = (const float*)d_in[1];  // [784]
    const float* sre = (const float*)d_in[2];  // [784, 200]
    const float* sim = (const float*)d_in[3];  // [784, 200]
    const float* ere = (const float*)d_in[4];  // [200]
    const float* eim = (const float*)d_in[5];  // [200]
    const float* wre = (const float*)d_in[6];  // [200]
    const float* wim = (const float*)d_in[7];  // [200]
    const float* lw  = (const float*)d_in[8];  // [10, 10]
    const float* lb  = (const float*)d_in[9];  // [10]
    float* out = (float*)d_out;                // [256, 10] float32

    k_uc<<<dim3(PSPLIT + 1, BDIM / BTILE), TDIM>>>(x, v, sre, sim,
                                                   wre, wim, ere, eim);
    k_D<<<TDIM, TDIM>>>();
    k_out<<<BDIM / 2, TDIM>>>(lw, lb, out);
}